// round 16
// baseline (speedup 1.0000x reference)
#include <cuda_runtime.h>
#include <cuda_fp16.h>
#include <mma.h>
#include <math.h>

using namespace nvcuda;

#define N_NODES   50000
#define N_EDGES   1600000
#define N_GRAPHS  256
#define DIM_IN    128
#define D1        100
#define D2        20
#define DIM_SELF  64

#define P1_LD2    64          // p1 row stride in half2 (128 halfs = 256B aligned)
#define P1_ROWS   50048       // padded to 128-row multiple: unguarded wmma stores
#define P2_LD2    16          // p2 row stride in half2 (32 halfs = 64B aligned)
#define W1_LD     112         // padded W1 cols (halfs)
#define AH_LD     136         // Ah smem row stride in halfs (272B -> conflict-free LDSM)

// ---------------- scratch (device globals; no allocation allowed) -----------
// Invariant: g_cnt / g_hg / g_gcnt are zero on entry to every call (zero-init
// at load; re-zeroed by the kernels that consume them).
__device__ __align__(16) int     g_cnt[N_NODES];
__device__ __align__(16) int     g_rowptr[N_NODES + 1];
__device__ __align__(16) int     g_posn[N_EDGES];
__device__ __align__(16) int     g_csr[N_EDGES];
__device__ __align__(16) __half  g_w1h[128 * W1_LD];        // W1 fp16 (refreshed per call)
__device__ __align__(16) __half2 g_p1h[P1_ROWS * P1_LD2];   // feat @ W1 (fp16)
__device__ __align__(16) __half2 g_p2h[N_NODES * P2_LD2];   // h1 @ W2 (fp16)
__device__ __align__(16) float   g_hg[N_GRAPHS * D2];
__device__ __align__(16) int     g_gcnt[N_GRAPHS];

// ---------------- CSR count (single atomic pass) + W1 fp16 convert ----------
__global__ void k_count(const int* __restrict__ dst, const float* __restrict__ W1) {
    int e4 = blockIdx.x * blockDim.x + threadIdx.x;
    if (e4 < 128 * W1_LD) {                  // piggyback: W1 -> fp16
        int k = e4 / W1_LD, c = e4 - k * W1_LD;
        g_w1h[e4] = (c < D1) ? __float2half(W1[k * D1 + c]) : __float2half(0.f);
    }
    if (e4 >= N_EDGES / 4) return;
    int4 d = ((const int4*)dst)[e4];
    int4 p;
    p.x = atomicAdd(&g_cnt[d.x], 1);
    p.y = atomicAdd(&g_cnt[d.y], 1);
    p.z = atomicAdd(&g_cnt[d.z], 1);
    p.w = atomicAdd(&g_cnt[d.w], 1);
    ((int4*)g_posn)[e4] = p;
}

// single-block exclusive scan of g_cnt -> g_rowptr (int4, CH=52);
// re-zeroes g_cnt after reading (restores the call-entry invariant).
__global__ void k_scan() {
    __shared__ int ss[1024];
    const int CH = 52;                       // 13 int4 per thread
    int t = threadIdx.x;
    int base = t * CH;
    int s = 0;
    if (base + CH <= N_NODES) {
        const int4* p = (const int4*)(g_cnt + base);
        #pragma unroll
        for (int i = 0; i < 13; i++) { int4 v = p[i]; s += v.x + v.y + v.z + v.w; }
    } else {
        for (int i = base; i < N_NODES; i++) s += g_cnt[i];
    }
    ss[t] = s;
    __syncthreads();
    for (int off = 1; off < 1024; off <<= 1) {
        int v = (t >= off) ? ss[t - off] : 0;
        __syncthreads();
        ss[t] += v;
        __syncthreads();
    }
    int run = (t == 0) ? 0 : ss[t - 1];
    if (base + CH <= N_NODES) {
        const int4* p = (const int4*)(g_cnt + base);
        int4* q = (int4*)(g_rowptr + base);
        int4* z = (int4*)(g_cnt + base);
        #pragma unroll
        for (int i = 0; i < 13; i++) {
            int4 v = p[i];
            int4 o;
            o.x = run; run += v.x;
            o.y = run; run += v.y;
            o.z = run; run += v.z;
            o.w = run; run += v.w;
            q[i] = o;
            z[i] = make_int4(0, 0, 0, 0);
        }
    } else {
        for (int i = base; i < N_NODES; i++) {
            g_rowptr[i] = run; run += g_cnt[i]; g_cnt[i] = 0;
        }
    }
    if (t == 0) g_rowptr[N_NODES] = N_EDGES;
}

// atomic-free fill: slot known from recorded position
__global__ void k_fill(const int* __restrict__ src, const int* __restrict__ dst) {
    int e4 = blockIdx.x * blockDim.x + threadIdx.x;
    if (e4 >= N_EDGES / 4) return;
    int4 d = ((const int4*)dst)[e4];
    int4 p = ((const int4*)g_posn)[e4];
    int4 s = ((const int4*)src)[e4];
    g_csr[g_rowptr[d.x] + p.x] = s.x;
    g_csr[g_rowptr[d.y] + p.y] = s.y;
    g_csr[g_rowptr[d.z] + p.z] = s.z;
    g_csr[g_rowptr[d.w] + p.w] = s.w;
}

// ---------------- GEMM1: p1 = feat @ W1 via HMMA ----------------------------
// 128 rows/block, warp-per-column-tile: warps 0..6 each own one 16-col tile,
// preload their 8 B fragments into REGISTERS once, then sweep 8 row strips
// (A from conflict-free 272B-stride smem via LDSM, fp16 accs stored straight
// to padded g_p1h). B global traffic: 8 fragments per warp per block total.
__global__ void k_gemm1(const float* __restrict__ feat) {
    __shared__ __align__(16) __half Ah[128 * AH_LD];   // 34816 B
    int t  = threadIdx.x;
    int r0 = blockIdx.x * 128;

    for (int i = t; i < 128 * 32; i += 256) {
        int r = i >> 5, q = i & 31;
        float4 f = (r0 + r < N_NODES)
                 ? ((const float4*)feat)[(size_t)(r0 + r) * 32 + q]
                 : make_float4(0.f, 0.f, 0.f, 0.f);
        __half2* a2 = (__half2*)(Ah + r * AH_LD + q * 4);
        a2[0] = __floats2half2_rn(f.x, f.y);
        a2[1] = __floats2half2_rn(f.z, f.w);
    }
    __syncthreads();

    int w = t >> 5;
    if (w >= 7) return;                      // warps 0..6 compute (7 col tiles)

    // B fragments for this warp's col tile, register-resident for the block
    wmma::fragment<wmma::matrix_b, 16, 16, 16, __half, wmma::row_major> bf[8];
    #pragma unroll
    for (int k8 = 0; k8 < 8; k8++)
        wmma::load_matrix_sync(bf[k8], g_w1h + (k8 * 16) * W1_LD + w * 16, W1_LD);

    __half* out = (__half*)g_p1h;            // row stride 128 halfs; rows padded
    #pragma unroll
    for (int s = 0; s < 8; s++) {
        wmma::fragment<wmma::accumulator, 16, 16, 16, __half> acc;
        wmma::fill_fragment(acc, __float2half(0.f));
        #pragma unroll
        for (int k8 = 0; k8 < 8; k8++) {
            wmma::fragment<wmma::matrix_a, 16, 16, 16, __half, wmma::row_major> af;
            wmma::load_matrix_sync(af, Ah + (s * 16) * AH_LD + k8 * 16, AH_LD);
            wmma::mma_sync(acc, af, bf[k8], acc);
        }
        wmma::store_matrix_sync(out + (size_t)(r0 + s * 16) * 128 + w * 16,
                                acc, 128, wmma::mem_row_major);
    }
}

// ---------------- Fused: aggregation-1 + relu + GEMM2 (round-10 form) -------
// 8 warps, 1 node per warp; h1 row lands in smem; lanes 0..19 then do the
// 100x20 projection against smem W2 and write p2 (fp16).
__global__ void k_agg1g2(const float* __restrict__ b1, const float* __restrict__ W2) {
    __shared__ float h1s[8][104];
    __shared__ float w2s[D1 * D2];     // 8000 B
    int t = threadIdx.x, w = t >> 5, lane = t & 31;

    for (int i = t; i < D1 * D2; i += 256) w2s[i] = W2[i];

    int gw = blockIdx.x * 8 + w;       // grid*8 == N_NODES exactly
    int start = g_rowptr[gw], end = g_rowptr[gw + 1];
    int deg = end - start;
    float a0x = 0.f, a0y = 0.f, a1x = 0.f, a1y = 0.f;

    int nfull = deg & ~31;
    for (int eb = start; eb < start + nfull; eb += 32) {
        int s = g_csr[eb + lane];
        #pragma unroll 8
        for (int j = 0; j < 32; j++) {
            int sj = __shfl_sync(0xffffffffu, s, j);
            const __half2* row = g_p1h + (size_t)sj * P1_LD2;
            float2 v0 = __half22float2(row[lane]);
            a0x += v0.x; a0y += v0.y;
            if (lane < 18) {
                float2 v1 = __half22float2(row[32 + lane]);
                a1x += v1.x; a1y += v1.y;
            }
        }
    }
    int rem = deg - nfull;
    if (rem) {
        int s = (lane < rem) ? g_csr[start + nfull + lane] : 0;
        for (int j = 0; j < rem; j++) {
            int sj = __shfl_sync(0xffffffffu, s, j);
            const __half2* row = g_p1h + (size_t)sj * P1_LD2;
            float2 v0 = __half22float2(row[lane]);
            a0x += v0.x; a0y += v0.y;
            if (lane < 18) {
                float2 v1 = __half22float2(row[32 + lane]);
                a1x += v1.x; a1y += v1.y;
            }
        }
    }
    if (deg > 0) {
        float inv = 1.0f / (float)deg;
        a0x *= inv; a0y *= inv; a1x *= inv; a1y *= inv;
    } else {
        const __half2* row = g_p1h + (size_t)gw * P1_LD2;
        float2 v0 = __half22float2(row[lane]);
        a0x = v0.x; a0y = v0.y;
        if (lane < 18) {
            float2 v1 = __half22float2(row[32 + lane]);
            a1x = v1.x; a1y = v1.y;
        }
    }
    const float2* b1v = (const float2*)b1;
    float2 bb = b1v[lane];
    ((float2*)h1s[w])[lane] = make_float2(fmaxf(a0x + bb.x, 0.f),
                                          fmaxf(a0y + bb.y, 0.f));
    if (lane < 18) {
        float2 bc = b1v[32 + lane];
        ((float2*)h1s[w])[32 + lane] = make_float2(fmaxf(a1x + bc.x, 0.f),
                                                   fmaxf(a1y + bc.y, 0.f));
    }
    __syncthreads();

    // GEMM2: p2[gw][c] = sum_k h1s[w][k] * W2[k][c], c = lane < 20
    float acc = 0.f;
    if (lane < D2) {
        #pragma unroll
        for (int k = 0; k < D1; k++)
            acc += h1s[w][k] * w2s[k * D2 + lane];
    }
    float hi = __shfl_down_sync(0xffffffffu, acc, 1);
    if (lane < D2 && (lane & 1) == 0)
        g_p2h[(size_t)gw * P2_LD2 + (lane >> 1)] = __floats2half2_rn(acc, hi);
}

// ---------------- Aggregation layer 2 + fused pool (round-10 form) ----------
__global__ void k_agg2pool(const float* __restrict__ b2, const int* __restrict__ gid) {
    int gw   = (blockIdx.x * blockDim.x + threadIdx.x) >> 5;
    int lane = threadIdx.x & 31;
    int start = g_rowptr[gw], end = g_rowptr[gw + 1];
    int deg = end - start;
    int half = lane >> 4;       // 0: even edges, 1: odd edges
    int idx  = lane & 15;       // half2 index within row (<10 active)
    float ax = 0.f, ay = 0.f;
    for (int eb = start; eb < end; eb += 32) {
        int n = min(32, end - eb);
        int s = (lane < n) ? g_csr[eb + lane] : 0;
        for (int j = 0; j < n; j += 2) {
            int je = j + half;
            int sj = __shfl_sync(0xffffffffu, s, je);
            if (idx < 10 && je < n) {
                float2 v = __half22float2(g_p2h[(size_t)sj * P2_LD2 + idx]);
                ax += v.x; ay += v.y;
            }
        }
    }
    ax += __shfl_xor_sync(0xffffffffu, ax, 16);
    ay += __shfl_xor_sync(0xffffffffu, ay, 16);

    int g = gid[gw];
    if (lane < 10) {
        float vx, vy;
        if (deg > 0) {
            float inv = 1.0f / (float)deg;
            vx = ax * inv; vy = ay * inv;
        } else {
            float2 v = __half22float2(g_p2h[(size_t)gw * P2_LD2 + lane]);
            vx = v.x; vy = v.y;
        }
        const float2* b2v = (const float2*)b2;
        float2 bb = b2v[lane];
        atomicAdd(&g_hg[g * D2 + 2 * lane],     fmaxf(vx + bb.x, 0.f));
        atomicAdd(&g_hg[g * D2 + 2 * lane + 1], fmaxf(vy + bb.y, 0.f));
    }
    if (lane == 0) atomicAdd(&g_gcnt[g], 1);
}

// ---------------- gate + MLP decoder (256 graphs, 1 block) ------------------
// Re-zeroes g_hg / g_gcnt after reading (restores the call-entry invariant).
__global__ void k_final(const float* __restrict__ self_feat,
                        const float* __restrict__ Wp,  const float* __restrict__ bp,
                        const float* __restrict__ Wf1, const float* __restrict__ bf1,
                        const float* __restrict__ Wf2, const float* __restrict__ bf2,
                        float* __restrict__ out) {
    __shared__ float swp[DIM_SELF * D2];
    __shared__ float sbp[D2], swf1[D2 * 10], sbf1[10], swf2[10], sbf2;
    int t = threadIdx.x;
    for (int i = t; i < DIM_SELF * D2; i += 256) swp[i] = Wp[i];
    for (int i = t; i < D2 * 10; i += 256) swf1[i] = Wf1[i];
    if (t < D2) sbp[t] = bp[t];
    if (t < 10) { sbf1[t] = bf1[t]; swf2[t] = Wf2[t]; }
    if (t == 0) sbf2 = bf2[0];
    __syncthreads();

    int g = t;
    float hg[D2], z[D2];
    int c = g_gcnt[g];
    float invc = 1.0f / (float)max(c, 1);
    #pragma unroll
    for (int j = 0; j < D2; j++) { hg[j] = g_hg[g * D2 + j] * invc; z[j] = sbp[j]; }
    #pragma unroll
    for (int j = 0; j < D2; j++) g_hg[g * D2 + j] = 0.f;   // restore invariant
    g_gcnt[g] = 0;

    for (int i = 0; i < DIM_SELF; i++) {
        float sv = self_feat[g * DIM_SELF + i];
        #pragma unroll
        for (int j = 0; j < D2; j++) z[j] += sv * swp[i * D2 + j];
    }
    float m[10];
    #pragma unroll
    for (int o = 0; o < 10; o++) m[o] = sbf1[o];
    #pragma unroll
    for (int j = 0; j < D2; j++) {
        float p    = hg[j] * z[j];
        float gate = 1.0f / (1.0f + expf(-p));
        float f    = gate * hg[j] + (1.0f - gate) * z[j];
        #pragma unroll
        for (int o = 0; o < 10; o++) m[o] += f * swf1[j * 10 + o];
    }
    float o0 = sbf2;
    #pragma unroll
    for (int o = 0; o < 10; o++) o0 += fmaxf(m[o], 0.f) * swf2[o];
    out[g] = o0;
}

// ---------------- launch -----------------------------------------------------
extern "C" void kernel_launch(void* const* d_in, const int* in_sizes, int n_in,
                              void* d_out, int out_size) {
    const float* feat      = (const float*)d_in[0];
    const int*   src       = (const int*)  d_in[1];
    const int*   dst       = (const int*)  d_in[2];
    const int*   gid       = (const int*)  d_in[3];
    const float* self_feat = (const float*)d_in[4];
    const float* W1  = (const float*)d_in[5];
    const float* b1  = (const float*)d_in[6];
    const float* W2  = (const float*)d_in[7];
    const float* b2  = (const float*)d_in[8];
    const float* Wp  = (const float*)d_in[9];
    const float* bp  = (const float*)d_in[10];
    const float* Wf1 = (const float*)d_in[11];
    const float* bf1 = (const float*)d_in[12];
    const float* Wf2 = (const float*)d_in[13];
    const float* bf2 = (const float*)d_in[14];
    float* out = (float*)d_out;

    k_count   <<<(N_EDGES / 4 + 255) / 256, 256>>>(dst, W1);
    k_scan    <<<1, 1024>>>();
    k_fill    <<<(N_EDGES / 4 + 255) / 256, 256>>>(src, dst);
    k_gemm1   <<<P1_ROWS / 128, 256>>>(feat);
    k_agg1g2  <<<N_NODES / 8, 256>>>(b1, W2);
    k_agg2pool<<<N_NODES / 8, 256>>>(b2, gid);
    k_final   <<<1, 256>>>(self_feat, Wp, bp, Wf1, bf1, Wf2, bf2, out);
}